// round 16
// baseline (speedup 1.0000x reference)
#include <cuda_runtime.h>
#include <math.h>
#include <stdint.h>

#define Nn 20000
#define IN_DIMc 1536
#define HIDc 256
#define HEADSc 4
#define HDc 64
#define HOPSc 3
#define NCLSc 3
#define EMAXc 400000
#define EPSV 1e-5f
#define NEG_SLOPE 0.2f

// ---------------- scratch (device globals; no allocations) ----------------
__device__ float g_X[Nn * HIDc];     // exact activations (residual path)
__device__ float g_Xr[Nn * HIDc];    // tf32-pre-rounded copy (GEMM A operand)
__device__ float g_tmp[Nn * HIDc];
__device__ float g_XL[Nn * HIDc];
__device__ float g_XR[Nn * HIDc];
__device__ int g_deg[Nn];
__device__ int g_rowptr[Nn + 1];
__device__ int g_cursor[Nn];
__device__ int g_esrc[EMAXc];
__device__ int g_flag;  // 1 = edge_index is int64, 0 = int32
// tf32-pre-rounded weights
__device__ float g_cprojW[IN_DIMc * HIDc];
__device__ float g_cWl[HOPSc * HIDc * HIDc];
__device__ float g_cWr[HOPSc * HIDc * HIDc];
__device__ float g_ch1W[HIDc * HIDc];

// ---------------- f32x2 packed helpers (sm_103a) ----------------
#define MUL2(out, a, b) \
    asm("mul.rn.f32x2 %0, %1, %2;" : "=l"(out) : "l"(a), "l"(b))
#define ADD2(out, a, b) \
    asm("add.rn.f32x2 %0, %1, %2;" : "=l"(out) : "l"(a), "l"(b))
#define FMA2(out, a, b, c) \
    asm("fma.rn.f32x2 %0, %1, %2, %3;" : "=l"(out) : "l"(a), "l"(b), "l"(c))
#define PACK2(out, lo, hi) \
    asm("mov.b64 %0, {%1, %2};" : "=l"(out) : "f"(lo), "f"(hi))
#define UNPACK2(lo, hi, in) \
    asm("mov.b64 {%0, %1}, %2;" : "=f"(lo), "=f"(hi) : "l"(in))

// ---------------- dtype probe ----------------
__global__ void detect_idx_kernel(const void* __restrict__ ei) {
    if (threadIdx.x == 0 && blockIdx.x == 0) {
        const long long* p = (const long long*)ei;
        int ok = 1;
        for (int i = 0; i < 256; i++) {
            long long v = p[i];
            if (v < 0 || v >= (long long)Nn) { ok = 0; break; }
        }
        g_flag = ok;
    }
}

__device__ __forceinline__ int edge_get(const void* ei, long long idx, int flag) {
    return flag ? (int)((const long long*)ei)[idx] : ((const int*)ei)[idx];
}

// ---------------- tf32 helpers ----------------
__device__ __forceinline__ uint32_t cvt_tf32(uint32_t bits) {
    float f = __uint_as_float(bits);
    uint32_t r;
    asm("cvt.rna.tf32.f32 %0, %1;" : "=r"(r) : "f"(f));
    return r;
}
__device__ __forceinline__ float round_tf32(float f) {
    return __uint_as_float(cvt_tf32(__float_as_uint(f)));
}

__global__ void cvt_w_kernel(const float* __restrict__ src, float* __restrict__ dst, int n) {
    int i = blockIdx.x * blockDim.x + threadIdx.x;
    if (i < n) dst[i] = round_tf32(src[i]);
}

// ---------------- CSR build ----------------
__global__ void deg_zero_kernel() {
    int i = blockIdx.x * blockDim.x + threadIdx.x;
    if (i < Nn) g_deg[i] = 0;
}

__global__ void hist_kernel(const void* __restrict__ ei, int E) {
    int e = blockIdx.x * blockDim.x + threadIdx.x;
    if (e >= E) return;
    int dst = edge_get(ei, (long long)E + e, g_flag);
    atomicAdd(&g_deg[dst], 1);
}

__global__ void scan_kernel() {
    const int PER = 20;
    __shared__ int wsum[32];
    __shared__ int wexcl[32];
    int tid = threadIdx.x, lane = tid & 31, wid = tid >> 5;
    int base = tid * PER;

    int deg[PER];
    int tot = 0;
#pragma unroll
    for (int i = 0; i < PER; i++) {
        int idx = base + i;
        deg[i] = (idx < Nn) ? g_deg[idx] : 0;
        tot += deg[i];
    }
    int incl = tot;
#pragma unroll
    for (int o = 1; o < 32; o <<= 1) {
        int t = __shfl_up_sync(0xffffffffu, incl, o);
        if (lane >= o) incl += t;
    }
    if (lane == 31) wsum[wid] = incl;
    __syncthreads();
    if (wid == 0) {
        int v = wsum[lane];
        int s = v;
#pragma unroll
        for (int o = 1; o < 32; o <<= 1) {
            int t = __shfl_up_sync(0xffffffffu, s, o);
            if (lane >= o) s += t;
        }
        wexcl[lane] = s - v;
    }
    __syncthreads();

    int running = wexcl[wid] + (incl - tot);
#pragma unroll
    for (int i = 0; i < PER; i++) {
        int idx = base + i;
        if (idx < Nn) {
            g_cursor[idx] = running;
            running += deg[i];
            g_rowptr[idx + 1] = running;
        }
    }
    if (tid == 0) g_rowptr[0] = 0;
}

__global__ void fill_kernel(const void* __restrict__ ei, int E) {
    int e = blockIdx.x * blockDim.x + threadIdx.x;
    if (e >= E) return;
    int flag = g_flag;
    int src = edge_get(ei, e, flag);
    int dst = edge_get(ei, (long long)E + e, flag);
    int pos = atomicAdd(&g_cursor[dst], 1);
    g_esrc[pos] = src;
}

// ---------------- TF32 tensor-core GEMM (BK=32, 2-stage cp.async) --------
__device__ __forceinline__ void mma_tf32(float* c, uint32_t a0, uint32_t a1,
                                         uint32_t a2, uint32_t a3,
                                         uint32_t b0, uint32_t b1) {
    asm volatile(
        "mma.sync.aligned.m16n8k8.row.col.f32.tf32.tf32.f32 "
        "{%0,%1,%2,%3}, {%4,%5,%6,%7}, {%8,%9}, {%0,%1,%2,%3};"
        : "+f"(c[0]), "+f"(c[1]), "+f"(c[2]), "+f"(c[3])
        : "r"(a0), "r"(a1), "r"(a2), "r"(a3), "r"(b0), "r"(b1));
}

__device__ __forceinline__ void cp16(uint32_t saddr, const float* gptr) {
    asm volatile("cp.async.ca.shared.global [%0], [%1], 16;" ::"r"(saddr), "l"(gptr));
}

#define BKc 32
#define ASTRIDE 36
#define BSTRIDE 136
#define AWORDS (128 * ASTRIDE)
#define BWORDS (BKc * BSTRIDE)
#define GEMM_SMEM (2 * (AWORDS + BWORDS) * 4)

template <bool CVTA>
__global__ __launch_bounds__(256, 2)
void gemm_tc_kernel(const float* __restrict__ A,
                    const float* __restrict__ B0, const float* __restrict__ B1,
                    const float* __restrict__ bias0, const float* __restrict__ bias1,
                    float* __restrict__ C0, float* __restrict__ C1,
                    int M, int K, int Nc) {
    const float* __restrict__ B = blockIdx.z ? B1 : B0;
    const float* __restrict__ bias = blockIdx.z ? bias1 : bias0;
    float* __restrict__ C = blockIdx.z ? C1 : C0;

    extern __shared__ __align__(16) uint32_t dyn[];
    uint32_t* Asm = dyn;
    uint32_t* Bsm = dyn + 2 * AWORDS;

    int tid = threadIdx.x;
    int rm = blockIdx.x * 128, cn = blockIdx.y * 128;

    int arow = tid >> 3, aq = (tid & 7) * 4;
    int bkr = tid >> 5, bq = (tid & 31) * 4;

    const float* ga[4];
    uint32_t sAa[2][4], sBa[2][4];
#pragma unroll
    for (int p = 0; p < 4; p++) {
        int r = arow + p * 32;
        ga[p] = A + (size_t)min(rm + r, M - 1) * K + aq;
#pragma unroll
        for (int s = 0; s < 2; s++)
            sAa[s][p] = (uint32_t)__cvta_generic_to_shared(Asm + s * AWORDS + r * ASTRIDE + aq);
    }
    const float* gb[4];
#pragma unroll
    for (int p = 0; p < 4; p++) {
        int kr = bkr + p * 8;
        gb[p] = B + (size_t)kr * Nc + cn + bq;
#pragma unroll
        for (int s = 0; s < 2; s++)
            sBa[s][p] = (uint32_t)__cvta_generic_to_shared(Bsm + s * BWORDS + kr * BSTRIDE + bq);
    }

    int warp = tid >> 5, lane = tid & 31, grp = lane >> 2, qid = lane & 3;
    int wm = (warp & 3) * 32, wn = (warp >> 2) * 64;

    float acc[2][8][4];
#pragma unroll
    for (int mt = 0; mt < 2; mt++)
#pragma unroll
        for (int nt = 0; nt < 8; nt++)
#pragma unroll
            for (int i = 0; i < 4; i++) acc[mt][nt][i] = 0.f;

    int ntile = K / BKc;

#pragma unroll
    for (int p = 0; p < 4; p++) {
        cp16(sAa[0][p], ga[p]);
        cp16(sBa[0][p], gb[p]);
    }
    asm volatile("cp.async.commit_group;");

    int s = 0;
    for (int t = 0; t < ntile; t++) {
        if (t + 1 < ntile) {
            int kt = (t + 1) * BKc;
#pragma unroll
            for (int p = 0; p < 4; p++) {
                cp16(sAa[s ^ 1][p], ga[p] + kt);
                cp16(sBa[s ^ 1][p], gb[p] + (size_t)kt * Nc);
            }
            asm volatile("cp.async.commit_group;");
            asm volatile("cp.async.wait_group 1;");
        } else {
            asm volatile("cp.async.wait_group 0;");
        }
        __syncthreads();

        const uint32_t* As = Asm + s * AWORDS;
        const uint32_t* Bs = Bsm + s * BWORDS;
#pragma unroll
        for (int ks = 0; ks < BKc; ks += 8) {
            uint32_t af[2][4];
#pragma unroll
            for (int mt = 0; mt < 2; mt++) {
                int m = wm + mt * 16 + grp;
                if (CVTA) {
                    af[mt][0] = cvt_tf32(As[m * ASTRIDE + ks + qid]);
                    af[mt][1] = cvt_tf32(As[(m + 8) * ASTRIDE + ks + qid]);
                    af[mt][2] = cvt_tf32(As[m * ASTRIDE + ks + qid + 4]);
                    af[mt][3] = cvt_tf32(As[(m + 8) * ASTRIDE + ks + qid + 4]);
                } else {
                    af[mt][0] = As[m * ASTRIDE + ks + qid];
                    af[mt][1] = As[(m + 8) * ASTRIDE + ks + qid];
                    af[mt][2] = As[m * ASTRIDE + ks + qid + 4];
                    af[mt][3] = As[(m + 8) * ASTRIDE + ks + qid + 4];
                }
            }
#pragma unroll
            for (int nt = 0; nt < 8; nt++) {
                int n = wn + nt * 8 + grp;
                uint32_t b0 = Bs[(ks + qid) * BSTRIDE + n];
                uint32_t b1 = Bs[(ks + qid + 4) * BSTRIDE + n];
                mma_tf32(acc[0][nt], af[0][0], af[0][1], af[0][2], af[0][3], b0, b1);
                mma_tf32(acc[1][nt], af[1][0], af[1][1], af[1][2], af[1][3], b0, b1);
            }
        }
        __syncthreads();
        s ^= 1;
    }

#pragma unroll
    for (int nt = 0; nt < 8; nt++) {
        int gcol = cn + wn + nt * 8 + qid * 2;
        float2 bb = *(const float2*)(bias + gcol);
#pragma unroll
        for (int mt = 0; mt < 2; mt++) {
            int r0 = rm + wm + mt * 16 + grp;
            int r1 = r0 + 8;
            if (r0 < M) {
                float2 o = make_float2(acc[mt][nt][0] + bb.x, acc[mt][nt][1] + bb.y);
                *(float2*)(C + (size_t)r0 * Nc + gcol) = o;
            }
            if (r1 < M) {
                float2 o = make_float2(acc[mt][nt][2] + bb.x, acc[mt][nt][3] + bb.y);
                *(float2*)(C + (size_t)r1 * Nc + gcol) = o;
            }
        }
    }
}

// ---------------- fused edge aggregation + bias/residual/LN --------------
// Warp per dst. Issue-bound -> minimize per-edge instructions:
//  * no online-max rescale (logits bounded: |s| << 80, exp safe; exact math
//    identity exp(s)/sum == exp(s-m)/sum(exp(s-m)))
//  * packed f32x2 math; leaky(v) = 0.6v + 0.4|v| (exact identity)
__global__ __launch_bounds__(256)
void edge_agg_kernel(const float* __restrict__ XL, const float* __restrict__ XR,
                     const float* __restrict__ att,
                     const float* __restrict__ gbias,
                     const float* __restrict__ lng, const float* __restrict__ lnb,
                     float* __restrict__ X, float* __restrict__ Xr) {
    int n = blockIdx.x * 8 + (threadIdx.x >> 5);
    if (n >= Nn) return;
    int lane = threadIdx.x & 31;

    const uint64_t ABSM = 0x7FFFFFFF7FFFFFFFULL;
    uint64_t c04, c06;
    PACK2(c04, 0.4f, 0.4f);
    PACK2(c06, 0.6f, 0.6f);

    // lane's 8 columns as 4 f32x2 pairs
    const ulonglong2* xr16 = (const ulonglong2*)(XR + (size_t)n * HIDc) + lane * 2;
    ulonglong2 xq0 = xr16[0], xq1 = xr16[1];
    uint64_t xrp[4] = {xq0.x, xq0.y, xq1.x, xq1.y};
    const ulonglong2* at16 = (const ulonglong2*)att + lane * 2;
    ulonglong2 aq0 = at16[0], aq1 = at16[1];
    uint64_t atp[4] = {aq0.x, aq0.y, aq1.x, aq1.y};

    float d = 0.f;
    uint64_t acc2[4];
    PACK2(acc2[0], 0.f, 0.f);
    acc2[1] = acc2[0]; acc2[2] = acc2[0]; acc2[3] = acc2[0];

    int beg = g_rowptr[n], end = g_rowptr[n + 1];
    int nE = end - beg;  // real in-edges; self loop appended at i == nE

    int sn2 = (1 < nE) ? __ldg(g_esrc + beg + 1) : n;
    int sn1 = (0 < nE) ? __ldg(g_esrc + beg) : n;
    const ulonglong2* p16 = (const ulonglong2*)(XL + (size_t)sn1 * HIDc) + lane * 2;
    ulonglong2 cq0 = p16[0], cq1 = p16[1];

    for (int i = 0; i <= nE; i++) {
        uint64_t a[4] = {cq0.x, cq0.y, cq1.x, cq1.y};
        if (i < nE) {
            const ulonglong2* q = (const ulonglong2*)(XL + (size_t)sn2 * HIDc) + lane * 2;
            cq0 = q[0];
            cq1 = q[1];
        }
        sn2 = (i + 2 < nE) ? __ldg(g_esrc + beg + i + 2) : n;

        // packed logit: s2 += leaky(a+xr) * att
        uint64_t s2;
        PACK2(s2, 0.f, 0.f);
#pragma unroll
        for (int p = 0; p < 4; p++) {
            uint64_t v, t, lk;
            ADD2(v, a[p], xrp[p]);
            uint64_t av = v & ABSM;
            MUL2(t, av, c04);
            FMA2(lk, v, c06, t);
            FMA2(s2, lk, atp[p], s2);
        }
        float sl, sh;
        UNPACK2(sl, sh, s2);
        float s = sl + sh;
        s += __shfl_xor_sync(0xffffffffu, s, 1);
        s += __shfl_xor_sync(0xffffffffu, s, 2);
        s += __shfl_xor_sync(0xffffffffu, s, 4);

        float w = __expf(s);
        d += w;
        uint64_t w2;
        PACK2(w2, w, w);
#pragma unroll
        for (int p = 0; p < 4; p++) FMA2(acc2[p], w2, a[p], acc2[p]);
    }

    float acc[8];
    UNPACK2(acc[0], acc[1], acc2[0]);
    UNPACK2(acc[2], acc[3], acc2[1]);
    UNPACK2(acc[4], acc[5], acc2[2]);
    UNPACK2(acc[6], acc[7], acc2[3]);

    float inv = 1.f / d;
    float4* xrow = (float4*)(X + (size_t)n * HIDc) + lane * 2;
    float4 x0 = xrow[0], x1 = xrow[1];
    const float4* gb4 = (const float4*)gbias + lane * 2;
    float4 gb0 = gb4[0], gb1 = gb4[1];
    float v[8];
    v[0] = acc[0] * inv + gb0.x + x0.x;
    v[1] = acc[1] * inv + gb0.y + x0.y;
    v[2] = acc[2] * inv + gb0.z + x0.z;
    v[3] = acc[3] * inv + gb0.w + x0.w;
    v[4] = acc[4] * inv + gb1.x + x1.x;
    v[5] = acc[5] * inv + gb1.y + x1.y;
    v[6] = acc[6] * inv + gb1.z + x1.z;
    v[7] = acc[7] * inv + gb1.w + x1.w;

    float s = 0.f, sq = 0.f;
#pragma unroll
    for (int j = 0; j < 8; j++) { s += v[j]; sq += v[j] * v[j]; }
#pragma unroll
    for (int o = 16; o > 0; o >>= 1) {
        s += __shfl_xor_sync(0xffffffffu, s, o);
        sq += __shfl_xor_sync(0xffffffffu, sq, o);
    }
    float mu = s * (1.f / HIDc);
    float var = sq * (1.f / HIDc) - mu * mu;
    float rs = rsqrtf(var + EPSV);

    const float4* lg4 = (const float4*)lng + lane * 2;
    const float4* lb4 = (const float4*)lnb + lane * 2;
    float4 lg0 = lg4[0], lg1 = lg4[1];
    float4 lb0 = lb4[0], lb1 = lb4[1];
    float4 o0, o1;
    o0.x = (v[0] - mu) * rs * lg0.x + lb0.x;
    o0.y = (v[1] - mu) * rs * lg0.y + lb0.y;
    o0.z = (v[2] - mu) * rs * lg0.z + lb0.z;
    o0.w = (v[3] - mu) * rs * lg0.w + lb0.w;
    o1.x = (v[4] - mu) * rs * lg1.x + lb1.x;
    o1.y = (v[5] - mu) * rs * lg1.y + lb1.y;
    o1.z = (v[6] - mu) * rs * lg1.z + lb1.z;
    o1.w = (v[7] - mu) * rs * lg1.w + lb1.w;
    xrow[0] = o0;
    xrow[1] = o1;

    float4* xrr = (float4*)(Xr + (size_t)n * HIDc) + lane * 2;
    float4 r0, r1;
    r0.x = round_tf32(o0.x); r0.y = round_tf32(o0.y);
    r0.z = round_tf32(o0.z); r0.w = round_tf32(o0.w);
    r1.x = round_tf32(o1.x); r1.y = round_tf32(o1.y);
    r1.z = round_tf32(o1.z); r1.w = round_tf32(o1.w);
    xrr[0] = r0;
    xrr[1] = r1;
}

// ---------------- input LN (once, after proj); dual exact/rounded out ----
__device__ __forceinline__ void block_mean_var_256(float v, float* smem, float& mu, float& var) {
    float s = v, sq = v * v;
#pragma unroll
    for (int o = 16; o > 0; o >>= 1) {
        s += __shfl_xor_sync(0xffffffffu, s, o);
        sq += __shfl_xor_sync(0xffffffffu, sq, o);
    }
    int w = threadIdx.x >> 5, l = threadIdx.x & 31;
    if (l == 0) { smem[w] = s; smem[8 + w] = sq; }
    __syncthreads();
    if (w == 0) {
        s = (l < 8) ? smem[l] : 0.f;
        sq = (l < 8) ? smem[8 + l] : 0.f;
#pragma unroll
        for (int o = 4; o > 0; o >>= 1) {
            s += __shfl_xor_sync(0xffffffffu, s, o);
            sq += __shfl_xor_sync(0xffffffffu, sq, o);
        }
        if (l == 0) { smem[0] = s; smem[8] = sq; }
    }
    __syncthreads();
    mu = smem[0] * (1.f / HIDc);
    var = smem[8] * (1.f / HIDc) - mu * mu;
}

__global__ void ln_kernel(const float* __restrict__ in, const float* __restrict__ g,
                          const float* __restrict__ b, float* __restrict__ out,
                          float* __restrict__ outr) {
    __shared__ float smem[16];
    int n = blockIdx.x, c = threadIdx.x;
    float v = in[(size_t)n * HIDc + c];
    float mu, var;
    block_mean_var_256(v, smem, mu, var);
    float o = (v - mu) * rsqrtf(var + EPSV) * g[c] + b[c];
    out[(size_t)n * HIDc + c] = o;
    outr[(size_t)n * HIDc + c] = round_tf32(o);
}

// ---------------- head: GELU(T) @ h2_W + h2_b, warp per node -------------
__global__ void head2_kernel(const float* __restrict__ T, const float* __restrict__ W2,
                             const float* __restrict__ b2, float* __restrict__ out) {
    int n = blockIdx.x * 8 + (threadIdx.x >> 5);
    if (n >= Nn) return;
    int lane = threadIdx.x & 31;
    const float* t = T + (size_t)n * HIDc;
    float a0 = 0.f, a1 = 0.f, a2 = 0.f;
#pragma unroll
    for (int j = 0; j < 8; j++) {
        int k = j * 32 + lane;
        float x = t[k];
        float ge = 0.5f * x * (1.f + erff(x * 0.70710678118654752440f));
        a0 += ge * W2[k * 3 + 0];
        a1 += ge * W2[k * 3 + 1];
        a2 += ge * W2[k * 3 + 2];
    }
#pragma unroll
    for (int o = 16; o > 0; o >>= 1) {
        a0 += __shfl_xor_sync(0xffffffffu, a0, o);
        a1 += __shfl_xor_sync(0xffffffffu, a1, o);
        a2 += __shfl_xor_sync(0xffffffffu, a2, o);
    }
    if (lane == 0) {
        out[n * 3 + 0] = a0 + b2[0];
        out[n * 3 + 1] = a1 + b2[1];
        out[n * 3 + 2] = a2 + b2[2];
    }
}

// ---------------- launcher ----------------
extern "C" void kernel_launch(void* const* d_in, const int* in_sizes, int n_in,
                              void* d_out, int out_size) {
    const float* features = (const float*)d_in[0];
    const void* ei = d_in[1];
    const float* proj_W = (const float*)d_in[2];
    const float* proj_b = (const float*)d_in[3];
    const float* n0_g = (const float*)d_in[4];
    const float* n0_b = (const float*)d_in[5];
    const float* Wl = (const float*)d_in[6];
    const float* bl = (const float*)d_in[7];
    const float* Wr = (const float*)d_in[8];
    const float* br = (const float*)d_in[9];
    const float* att = (const float*)d_in[10];
    const float* gbias = (const float*)d_in[11];
    const float* ln_g = (const float*)d_in[12];
    const float* ln_b = (const float*)d_in[13];
    const float* h1_W = (const float*)d_in[14];
    const float* h1_b = (const float*)d_in[15];
    const float* h2_W = (const float*)d_in[16];
    const float* h2_b = (const float*)d_in[17];
    float* out = (float*)d_out;

    int E = in_sizes[1] / 2;

    float *pX, *pXr, *pTmp, *pXL, *pXR, *pcProj, *pcWl, *pcWr, *pcH1;
    cudaGetSymbolAddress((void**)&pX, g_X);
    cudaGetSymbolAddress((void**)&pXr, g_Xr);
    cudaGetSymbolAddress((void**)&pTmp, g_tmp);
    cudaGetSymbolAddress((void**)&pXL, g_XL);
    cudaGetSymbolAddress((void**)&pXR, g_XR);
    cudaGetSymbolAddress((void**)&pcProj, g_cprojW);
    cudaGetSymbolAddress((void**)&pcWl, g_cWl);
    cudaGetSymbolAddress((void**)&pcWr, g_cWr);
    cudaGetSymbolAddress((void**)&pcH1, g_ch1W);

    cudaFuncSetAttribute(gemm_tc_kernel<true>,
                         cudaFuncAttributeMaxDynamicSharedMemorySize, GEMM_SMEM);
    cudaFuncSetAttribute(gemm_tc_kernel<false>,
                         cudaFuncAttributeMaxDynamicSharedMemorySize, GEMM_SMEM);

    dim3 g1((Nn + 127) / 128, HIDc / 128, 1);
    dim3 g2((Nn + 127) / 128, HIDc / 128, 2);
    int nodeWarpBlocks = (Nn + 7) / 8;

    cudaStream_t s2;
    cudaStreamCreateWithFlags(&s2, cudaStreamNonBlocking);
    cudaEvent_t evFork, evJoin;
    cudaEventCreateWithFlags(&evFork, cudaEventDisableTiming);
    cudaEventCreateWithFlags(&evJoin, cudaEventDisableTiming);

    detect_idx_kernel<<<1, 32>>>(ei);
    cvt_w_kernel<<<(IN_DIMc * HIDc + 255) / 256, 256>>>(proj_W, pcProj, IN_DIMc * HIDc);
    cudaEventRecord(evFork, 0);
    cudaStreamWaitEvent(s2, evFork, 0);

    cvt_w_kernel<<<(HOPSc * HIDc * HIDc + 255) / 256, 256, 0, s2>>>(Wl, pcWl, HOPSc * HIDc * HIDc);
    cvt_w_kernel<<<(HOPSc * HIDc * HIDc + 255) / 256, 256, 0, s2>>>(Wr, pcWr, HOPSc * HIDc * HIDc);
    cvt_w_kernel<<<(HIDc * HIDc + 255) / 256, 256, 0, s2>>>(h1_W, pcH1, HIDc * HIDc);
    deg_zero_kernel<<<(Nn + 255) / 256, 256, 0, s2>>>();
    hist_kernel<<<(E + 255) / 256, 256, 0, s2>>>(ei, E);
    scan_kernel<<<1, 1024, 0, s2>>>();
    fill_kernel<<<(E + 255) / 256, 256, 0, s2>>>(ei, E);
    cudaEventRecord(evJoin, s2);

    gemm_tc_kernel<true><<<g1, 256, GEMM_SMEM>>>(features, pcProj, pcProj, proj_b, proj_b,
                                                 pTmp, pTmp, Nn, IN_DIMc, HIDc);
    ln_kernel<<<Nn, 256>>>(pTmp, n0_g, n0_b, pX, pXr);

    cudaStreamWaitEvent(0, evJoin, 0);

    for (int h = 0; h < HOPSc; h++) {
        const float* Wlh = pcWl + (size_t)h * HIDc * HIDc;
        const float* Wrh = pcWr + (size_t)h * HIDc * HIDc;
        gemm_tc_kernel<false><<<g2, 256, GEMM_SMEM>>>(pXr, Wlh, Wrh, bl + h * HIDc, br + h * HIDc,
                                                      pXL, pXR, Nn, HIDc, HIDc);
        edge_agg_kernel<<<nodeWarpBlocks, 256>>>(pXL, pXR, att + h * HEADSc * HDc,
                                                 gbias + h * HIDc,
                                                 ln_g + h * HIDc, ln_b + h * HIDc, pX, pXr);
    }

    gemm_tc_kernel<false><<<g1, 256, GEMM_SMEM>>>(pXr, pcH1, pcH1, h1_b, h1_b,
                                                  pTmp, pTmp, Nn, HIDc, HIDc);
    head2_kernel<<<(Nn + 7) / 8, 256>>>(pTmp, h2_W, h2_b, out);

    cudaEventDestroy(evFork);
    cudaEventDestroy(evJoin);
    cudaStreamDestroy(s2);
}